// round 1
// baseline (speedup 1.0000x reference)
#include <cuda_runtime.h>

#define NB 4
#define DK 256
#define DV 516
#define HW 4096
#define LM 32

// temp = log2(32*64*64 + 64*64) / sqrt(256)
#define TEMP 1.06527463f

// Scratch (static device allocations are allowed; no cudaMalloc anywhere)
__device__ float g_q[NB * DK * HW];      // 16 MB: q[b][d][hw], pre-scaled by TEMP
__device__ float g_attn[NB * LM * HW];   // 2 MB:  attn[b][m][hw]

// ---------------------------------------------------------------------------
// Kernel 1: q[b][d][hw] = TEMP * sum_c fc[b][c][hw] * Q[c][d]
// Per batch: (d=256) x (hw=4096) output, K=256. Block tile 64(d) x 128(hw),
// BK=16, 256 threads, 4x8 register tile per thread.
// ---------------------------------------------------------------------------
__global__ __launch_bounds__(256) void qproj_kernel(
    const float* __restrict__ fc, const float* __restrict__ Qm) {
    __shared__ float Qs[16][64];     // [c][d]
    __shared__ float Fs[16][128];    // [c][hw]

    const int b   = blockIdx.z;
    const int d0  = blockIdx.y * 64;
    const int hw0 = blockIdx.x * 128;
    const int tid = threadIdx.x;
    const int tx  = tid & 15;        // hw direction (x8)
    const int ty  = tid >> 4;        // d direction  (x4)

    const float* fcb = fc + (size_t)b * DK * HW;

    float acc[4][8];
#pragma unroll
    for (int i = 0; i < 4; i++)
#pragma unroll
        for (int j = 0; j < 8; j++) acc[i][j] = 0.0f;

    for (int k0 = 0; k0 < DK; k0 += 16) {
        // Load Q tile: 16x64 = 1024 floats, 1 float4 per thread
        {
            const int r  = tid >> 4;          // 0..15 (c within tile)
            const int c4 = (tid & 15) * 4;    // 0..60 (d within tile)
            *(float4*)&Qs[r][c4] =
                *(const float4*)(Qm + (k0 + r) * DK + d0 + c4);
        }
        // Load fc tile: 16x128 = 2048 floats, 2 float4 per thread
        {
            const int r = tid >> 4;
            const int c = (tid & 15) * 8;
            const float* src = fcb + (size_t)(k0 + r) * HW + hw0 + c;
            *(float4*)&Fs[r][c]     = *(const float4*)(src);
            *(float4*)&Fs[r][c + 4] = *(const float4*)(src + 4);
        }
        __syncthreads();

#pragma unroll
        for (int k = 0; k < 16; k++) {
            float a[4], bb[8];
            *(float4*)a        = *(const float4*)&Qs[k][ty * 4];
            *(float4*)bb       = *(const float4*)&Fs[k][tx * 8];
            *(float4*)(bb + 4) = *(const float4*)&Fs[k][tx * 8 + 4];
#pragma unroll
            for (int i = 0; i < 4; i++)
#pragma unroll
                for (int j = 0; j < 8; j++) acc[i][j] += a[i] * bb[j];
        }
        __syncthreads();
    }

    float* qo = g_q + (size_t)b * DK * HW;
#pragma unroll
    for (int i = 0; i < 4; i++) {
        const int d = d0 + ty * 4 + i;
        float* dst = qo + (size_t)d * HW + hw0 + tx * 8;
        float4 v0, v1;
        v0.x = acc[i][0] * TEMP; v0.y = acc[i][1] * TEMP;
        v0.z = acc[i][2] * TEMP; v0.w = acc[i][3] * TEMP;
        v1.x = acc[i][4] * TEMP; v1.y = acc[i][5] * TEMP;
        v1.z = acc[i][6] * TEMP; v1.w = acc[i][7] * TEMP;
        *(float4*)(dst)     = v0;
        *(float4*)(dst + 4) = v1;
    }
}

// ---------------------------------------------------------------------------
// Kernel 2: scores[b][m][hw] = sum_d q[b][d][hw] * key[m][d][hw]; softmax over m.
// One thread per pixel. Block = 64 threads = 16 hw x 4 batches, so the 4
// batches read identical key addresses at the same time (coalesced/broadcast
// + L1 hits) -> key DRAM traffic stays at 128MB, not 512MB.
// ---------------------------------------------------------------------------
__global__ __launch_bounds__(64) void attn_kernel(const float* __restrict__ key) {
    const int tid = threadIdx.x;
    const int hw  = blockIdx.x * 16 + (tid & 15);
    const int b   = tid >> 4;

    const float* qp = g_q + (size_t)b * DK * HW + hw;
    const float* kp = key + hw;

    float s[LM];
#pragma unroll
    for (int m = 0; m < LM; m++) s[m] = 0.0f;

    // 2x d-unroll for memory-level parallelism (~64 independent loads in flight)
    for (int d = 0; d < DK; d += 2) {
        const float q0 = qp[(size_t)d * HW];
        const float q1 = qp[(size_t)(d + 1) * HW];
#pragma unroll
        for (int m = 0; m < LM; m++) {
            s[m] += q0 * kp[(size_t)(m * DK + d) * HW];
            s[m] += q1 * kp[(size_t)(m * DK + d + 1) * HW];
        }
    }

    // softmax over the 32 memory entries (max-subtracted, like jax.nn.softmax)
    float mx = s[0];
#pragma unroll
    for (int m = 1; m < LM; m++) mx = fmaxf(mx, s[m]);
    float sum = 0.0f;
#pragma unroll
    for (int m = 0; m < LM; m++) {
        s[m] = __expf(s[m] - mx);
        sum += s[m];
    }
    const float inv = 1.0f / sum;

    float* ap = g_attn + (size_t)b * LM * HW + hw;
#pragma unroll
    for (int m = 0; m < LM; m++) ap[(size_t)m * HW] = s[m] * inv;
}

// ---------------------------------------------------------------------------
// Kernel 3: out[b][c][hw] = fm[b][c][hw] + 0.5 * sum_m attn[b][m][hw]*value[m][c][hw]
// Block = 256 threads = 64 hw x 4 batches (value shared across batches via L1),
// grid split 4-way over c for occupancy. attn lives in 32 registers per thread.
// ---------------------------------------------------------------------------
__global__ __launch_bounds__(256) void out_kernel(
    const float* __restrict__ fm, const float* __restrict__ val,
    float* __restrict__ out) {
    const int tid = threadIdx.x;
    const int hw  = blockIdx.x * 64 + (tid & 63);
    const int b   = tid >> 6;
    const int c0  = blockIdx.y * 129;   // 516 = 4 * 129

    float a[LM];
    const float* ap = g_attn + (size_t)b * LM * HW + hw;
#pragma unroll
    for (int m = 0; m < LM; m++) a[m] = ap[(size_t)m * HW];

    const float* vp  = val + hw;
    const float* fmp = fm + (size_t)b * DV * HW + hw;
    float*       op  = out + (size_t)b * DV * HW + hw;

    for (int c = c0; c < c0 + 129; c++) {
        float acc0 = 0.0f, acc1 = 0.0f, acc2 = 0.0f, acc3 = 0.0f;
#pragma unroll
        for (int m = 0; m < LM; m += 4) {
            acc0 += a[m + 0] * vp[(size_t)((m + 0) * DV + c) * HW];
            acc1 += a[m + 1] * vp[(size_t)((m + 1) * DV + c) * HW];
            acc2 += a[m + 2] * vp[(size_t)((m + 2) * DV + c) * HW];
            acc3 += a[m + 3] * vp[(size_t)((m + 3) * DV + c) * HW];
        }
        const float acc = (acc0 + acc1) + (acc2 + acc3);
        op[(size_t)c * HW] = fmp[(size_t)c * HW] + 0.5f * acc;
    }
}

// ---------------------------------------------------------------------------
// Launch. Inputs (metadata order): fc, fm, key_buffer, value_buffer, Q, K, V.
// Note: the reference's concat(...)[-32:] drops ALL newly-projected k/v entries
// (4 + 32 -> last 32 == the buffers), so K and V matrices are dead inputs.
// ---------------------------------------------------------------------------
extern "C" void kernel_launch(void* const* d_in, const int* in_sizes, int n_in,
                              void* d_out, int out_size) {
    const float* fc   = (const float*)d_in[0];
    const float* fm   = (const float*)d_in[1];
    const float* keyb = (const float*)d_in[2];
    const float* valb = (const float*)d_in[3];
    const float* Qm   = (const float*)d_in[4];
    float* out = (float*)d_out;

    qproj_kernel<<<dim3(HW / 128, DK / 64, NB), 256>>>(fc, Qm);
    attn_kernel<<<dim3(HW / 16), 64>>>(keyb);
    out_kernel<<<dim3(HW / 64, 4), 256>>>(fm, valb, out);
}

// round 2
// speedup vs baseline: 2.4026x; 2.4026x over previous
#include <cuda_runtime.h>

#define NB 4
#define DK 256
#define DV 516
#define HW 4096
#define LM 32

// temp = log2(32*64*64 + 64*64) / sqrt(256)
#define TEMP 1.06527463f

// Scratch (static device allocations only; no cudaMalloc anywhere)
__device__ float g_q[NB * DK * HW];      // 16 MB: q[b][d][hw], pre-scaled by TEMP
__device__ float g_attn[NB * LM * HW];   // 2 MB:  attn[b][m][hw]

// ---------------------------------------------------------------------------
// Kernel 1: q[b][d][hw] = TEMP * sum_c Q[c][d] * fc[b][c][hw]
// SGEMM: A = Q (c-major rows, 256x256), B = fc (c rows, 4096 cols per batch).
// Block tile 128(d) x 128(hw), BK=8, 256 threads, 8x8 register tile.
// Per k-step: 4 LDS.128 feed 64 FFMA -> FFMA/LDS balanced.
// ---------------------------------------------------------------------------
__global__ __launch_bounds__(256) void qproj_kernel(
    const float* __restrict__ fc, const float* __restrict__ Qm) {
    __shared__ float As[8][128];   // [c][d]
    __shared__ float Bs[8][128];   // [c][hw]

    const int b   = blockIdx.z;
    const int d0  = blockIdx.y * 128;
    const int hw0 = blockIdx.x * 128;
    const int tid = threadIdx.x;
    const int tx  = tid & 15;        // hw tile coord (x8)
    const int ty  = tid >> 4;        // d  tile coord (x8)

    const float* fcb = fc + (size_t)b * DK * HW;

    float acc[8][8];
#pragma unroll
    for (int i = 0; i < 8; i++)
#pragma unroll
        for (int j = 0; j < 8; j++) acc[i][j] = 0.0f;

    const int lr = tid >> 5;          // 0..7  (c within tile)
    const int lc = (tid & 31) * 4;    // 0..124

    for (int k0 = 0; k0 < DK; k0 += 8) {
        *(float4*)&As[lr][lc] = *(const float4*)(Qm + (size_t)(k0 + lr) * DK + d0 + lc);
        *(float4*)&Bs[lr][lc] = *(const float4*)(fcb + (size_t)(k0 + lr) * HW + hw0 + lc);
        __syncthreads();

#pragma unroll
        for (int k = 0; k < 8; k++) {
            float a[8], bb[8];
            *(float4*)(a)      = *(const float4*)&As[k][ty * 8];
            *(float4*)(a + 4)  = *(const float4*)&As[k][ty * 8 + 4];
            *(float4*)(bb)     = *(const float4*)&Bs[k][tx * 8];
            *(float4*)(bb + 4) = *(const float4*)&Bs[k][tx * 8 + 4];
#pragma unroll
            for (int i = 0; i < 8; i++)
#pragma unroll
                for (int j = 0; j < 8; j++) acc[i][j] += a[i] * bb[j];
        }
        __syncthreads();
    }

    float* qo = g_q + (size_t)b * DK * HW;
#pragma unroll
    for (int i = 0; i < 8; i++) {
        float* dst = qo + (size_t)(d0 + ty * 8 + i) * HW + hw0 + tx * 8;
        float4 v0, v1;
        v0.x = acc[i][0] * TEMP; v0.y = acc[i][1] * TEMP;
        v0.z = acc[i][2] * TEMP; v0.w = acc[i][3] * TEMP;
        v1.x = acc[i][4] * TEMP; v1.y = acc[i][5] * TEMP;
        v1.z = acc[i][6] * TEMP; v1.w = acc[i][7] * TEMP;
        *(float4*)(dst)     = v0;
        *(float4*)(dst + 4) = v1;
    }
}

// ---------------------------------------------------------------------------
// Kernel 2: scores[b][m][hw] = sum_d q[b][d][hw]*key[m][d][hw]; softmax over m.
// Block 256 = 16 hw x 4 batches x 4 m-splits (8 m each). All 8 warps of a
// block touch the SAME key lines (key independent of b; m-splits disjoint but
// interleaved in L1) -> key DRAM traffic ~128MB total. Grid 256 blocks.
// ---------------------------------------------------------------------------
__global__ __launch_bounds__(256) void attn_kernel(const float* __restrict__ key) {
    __shared__ float sc[LM][64];     // [m][pixel = b*16 + hw16]

    const int tid  = threadIdx.x;
    const int hw16 = tid & 15;
    const int b    = (tid >> 4) & 3;
    const int ms   = tid >> 6;               // m-split 0..3 (8 m each)
    const int hw   = blockIdx.x * 16 + hw16;

    const float* qp = g_q + (size_t)b * DK * HW + hw;
    const float* kp = key + (size_t)(ms * 8) * DK * HW + hw;

    float acc[8];
#pragma unroll
    for (int j = 0; j < 8; j++) acc[j] = 0.0f;

    for (int d = 0; d < DK; d += 2) {
        const float q0 = qp[(size_t)d * HW];
        const float q1 = qp[(size_t)(d + 1) * HW];
#pragma unroll
        for (int j = 0; j < 8; j++) {
            acc[j] += q0 * kp[(size_t)(j * DK + d) * HW];
            acc[j] += q1 * kp[(size_t)(j * DK + d + 1) * HW];
        }
    }

    const int p = (b << 4) | hw16;
#pragma unroll
    for (int j = 0; j < 8; j++) sc[ms * 8 + j][p] = acc[j];
    __syncthreads();

    if (tid < 64) {
        const int bb   = tid >> 4;
        const int hwg  = blockIdx.x * 16 + (tid & 15);
        float s[LM];
        float mx = -1e30f;
#pragma unroll
        for (int m = 0; m < LM; m++) { s[m] = sc[m][tid]; mx = fmaxf(mx, s[m]); }
        float sum = 0.0f;
#pragma unroll
        for (int m = 0; m < LM; m++) { s[m] = __expf(s[m] - mx); sum += s[m]; }
        const float inv = 1.0f / sum;
        float* ap = g_attn + (size_t)bb * LM * HW + hwg;
#pragma unroll
        for (int m = 0; m < LM; m++) ap[(size_t)m * HW] = s[m] * inv;
    }
}

// ---------------------------------------------------------------------------
// Kernel 3: out[b][c][hw] = fm[b][c][hw] + 0.5*sum_m attn[b][m][hw]*val[m][c][hw]
// Block 128 = 32 hw x 4 batches (the 4 batch warps hit the same val lines in
// L1). Grid (128 hw-tiles, 43 c-chunks), 12 c's per thread. attn held in regs.
// ---------------------------------------------------------------------------
__global__ __launch_bounds__(128) void out_kernel(
    const float* __restrict__ fm, const float* __restrict__ val,
    float* __restrict__ out) {
    const int tid = threadIdx.x;
    const int hw  = blockIdx.x * 32 + (tid & 31);
    const int b   = tid >> 5;
    const int c0  = blockIdx.y * 12;          // 516 = 43 * 12

    float a[LM];
    const float* ap = g_attn + (size_t)b * LM * HW + hw;
#pragma unroll
    for (int m = 0; m < LM; m++) a[m] = ap[(size_t)m * HW];

    const float* vp  = val + hw;
    const float* fmp = fm + (size_t)b * DV * HW + hw;
    float*       op  = out + (size_t)b * DV * HW + hw;

#pragma unroll 3
    for (int cc = 0; cc < 12; cc++) {
        const int c = c0 + cc;
        float acc0 = 0.0f, acc1 = 0.0f, acc2 = 0.0f, acc3 = 0.0f;
#pragma unroll
        for (int m = 0; m < LM; m += 4) {
            acc0 += a[m + 0] * vp[(size_t)((m + 0) * DV + c) * HW];
            acc1 += a[m + 1] * vp[(size_t)((m + 1) * DV + c) * HW];
            acc2 += a[m + 2] * vp[(size_t)((m + 2) * DV + c) * HW];
            acc3 += a[m + 3] * vp[(size_t)((m + 3) * DV + c) * HW];
        }
        const float acc = (acc0 + acc1) + (acc2 + acc3);
        op[(size_t)c * HW] = fmp[(size_t)c * HW] + 0.5f * acc;
    }
}

// ---------------------------------------------------------------------------
// Launch. Inputs (metadata order): fc, fm, key_buffer, value_buffer, Q, K, V.
// The reference's concat(new, buffer)[-32:] keeps exactly the buffers, so the
// K and V projection matrices are dead inputs; only q = fc@Q survives.
// ---------------------------------------------------------------------------
extern "C" void kernel_launch(void* const* d_in, const int* in_sizes, int n_in,
                              void* d_out, int out_size) {
    const float* fc   = (const float*)d_in[0];
    const float* fm   = (const float*)d_in[1];
    const float* keyb = (const float*)d_in[2];
    const float* valb = (const float*)d_in[3];
    const float* Qm   = (const float*)d_in[4];
    float* out = (float*)d_out;

    qproj_kernel<<<dim3(HW / 128, DK / 128, NB), 256>>>(fc, Qm);
    attn_kernel<<<dim3(HW / 16), 256>>>(keyb);
    out_kernel<<<dim3(HW / 32, 43), 128>>>(fm, valb, out);
}

// round 3
// speedup vs baseline: 5.2933x; 2.2032x over previous
#include <cuda_runtime.h>

#define NB 4
#define DK 256
#define DV 516
#define HW 4096
#define LM 32
#define DS 4            // d-splits inside attn block

// temp = log2(32*64*64 + 64*64) / sqrt(256)
#define TEMP 1.06527463f

// Scratch (static device allocations only; no cudaMalloc anywhere)
__device__ float g_q[NB * DK * HW];      // 16 MB: q[b][d][hw], pre-scaled by TEMP
__device__ float g_attn[NB * LM * HW];   // 2 MB:  attn[b][m][hw]

// ---------------------------------------------------------------------------
// Kernel 1: q[b][d][hw] = TEMP * sum_c Q[c][d] * fc[b][c][hw]
// 128x128 block tile, BK=8, 256 threads, 8x8 register tile, double-buffered
// smem with register prefetch -> one __syncthreads per k-tile.
// ---------------------------------------------------------------------------
__global__ __launch_bounds__(256) void qproj_kernel(
    const float* __restrict__ fc, const float* __restrict__ Qm) {
    __shared__ float As[2][8][128];   // [buf][c][d]
    __shared__ float Bs[2][8][128];   // [buf][c][hw]

    const int b   = blockIdx.z;
    const int d0  = blockIdx.y * 128;
    const int hw0 = blockIdx.x * 128;
    const int tid = threadIdx.x;
    const int tx  = tid & 15;        // hw tile coord (x8)
    const int ty  = tid >> 4;        // d  tile coord (x8)

    const float* fcb = fc + (size_t)b * DK * HW;

    const int lr = tid >> 5;          // 0..7  (c within tile)
    const int lc = (tid & 31) * 4;    // 0..124

    float acc[8][8];
#pragma unroll
    for (int i = 0; i < 8; i++)
#pragma unroll
        for (int j = 0; j < 8; j++) acc[i][j] = 0.0f;

    // preload k-tile 0
    float4 pa = *(const float4*)(Qm + (size_t)lr * DK + d0 + lc);
    float4 pb = *(const float4*)(fcb + (size_t)lr * HW + hw0 + lc);
    *(float4*)&As[0][lr][lc] = pa;
    *(float4*)&Bs[0][lr][lc] = pb;
    __syncthreads();

    int buf = 0;
    for (int k0 = 0; k0 < DK; k0 += 8) {
        const bool has_next = (k0 + 8) < DK;
        if (has_next) {
            pa = *(const float4*)(Qm + (size_t)(k0 + 8 + lr) * DK + d0 + lc);
            pb = *(const float4*)(fcb + (size_t)(k0 + 8 + lr) * HW + hw0 + lc);
        }

#pragma unroll
        for (int k = 0; k < 8; k++) {
            float a[8], bb[8];
            *(float4*)(a)      = *(const float4*)&As[buf][k][ty * 8];
            *(float4*)(a + 4)  = *(const float4*)&As[buf][k][ty * 8 + 4];
            *(float4*)(bb)     = *(const float4*)&Bs[buf][k][tx * 8];
            *(float4*)(bb + 4) = *(const float4*)&Bs[buf][k][tx * 8 + 4];
#pragma unroll
            for (int i = 0; i < 8; i++)
#pragma unroll
                for (int j = 0; j < 8; j++) acc[i][j] += a[i] * bb[j];
        }

        if (has_next) {
            *(float4*)&As[buf ^ 1][lr][lc] = pa;
            *(float4*)&Bs[buf ^ 1][lr][lc] = pb;
            __syncthreads();
            buf ^= 1;
        }
    }

    float* qo = g_q + (size_t)b * DK * HW;
#pragma unroll
    for (int i = 0; i < 8; i++) {
        float* dst = qo + (size_t)(d0 + ty * 8 + i) * HW + hw0 + tx * 8;
        float4 v0, v1;
        v0.x = acc[i][0] * TEMP; v0.y = acc[i][1] * TEMP;
        v0.z = acc[i][2] * TEMP; v0.w = acc[i][3] * TEMP;
        v1.x = acc[i][4] * TEMP; v1.y = acc[i][5] * TEMP;
        v1.z = acc[i][6] * TEMP; v1.w = acc[i][7] * TEMP;
        *(float4*)(dst)     = v0;
        *(float4*)(dst + 4) = v1;
    }
}

// ---------------------------------------------------------------------------
// Kernel 2: scores + softmax fused.
// Block 512 = 32 hw lanes x 4 ms (8 m each) x 4 ds (64 d each). Each thread
// computes all 4 batches (key element loaded ONCE -> no b instruction
// replication; full 128B coalesced loads). Partial scores reduced through
// 64KB dynamic smem; softmax done by the first 128 threads.
// ---------------------------------------------------------------------------
extern __shared__ float s_red[];   // [DS][LM][NB][32] = 64KB

__global__ __launch_bounds__(512) void attn_kernel(const float* __restrict__ key) {
    const int tid  = threadIdx.x;
    const int lane = tid & 31;           // hw
    const int ms   = (tid >> 5) & 3;     // m group (8 m)
    const int ds   = tid >> 7;           // d split (64 d)
    const int hw   = blockIdx.x * 32 + lane;

    // pointers: 4 q (per batch) + 8 key (per m), advanced by HW each d step
    const float* qp[NB];
#pragma unroll
    for (int b = 0; b < NB; b++)
        qp[b] = g_q + (size_t)b * DK * HW + (size_t)(ds * 64) * HW + hw;
    const float* kp[8];
#pragma unroll
    for (int j = 0; j < 8; j++)
        kp[j] = key + (size_t)(ms * 8 + j) * DK * HW + (size_t)(ds * 64) * HW + hw;

    float acc[NB][8];
#pragma unroll
    for (int b = 0; b < NB; b++)
#pragma unroll
        for (int j = 0; j < 8; j++) acc[b][j] = 0.0f;

#pragma unroll 2
    for (int d = 0; d < 64; d++) {
        float q0 = qp[0][0], q1 = qp[1][0], q2 = qp[2][0], q3 = qp[3][0];
#pragma unroll
        for (int j = 0; j < 8; j++) {
            const float kv = kp[j][0];
            acc[0][j] += q0 * kv;
            acc[1][j] += q1 * kv;
            acc[2][j] += q2 * kv;
            acc[3][j] += q3 * kv;
        }
#pragma unroll
        for (int b = 0; b < NB; b++) qp[b] += HW;
#pragma unroll
        for (int j = 0; j < 8; j++) kp[j] += HW;
    }

    // stash partials: s_red[ds][m][b][lane]
#pragma unroll
    for (int b = 0; b < NB; b++)
#pragma unroll
        for (int j = 0; j < 8; j++)
            s_red[(((ds * LM) + ms * 8 + j) * NB + b) * 32 + lane] = acc[b][j];
    __syncthreads();

    // softmax: 128 threads = 32 hw x 4 b
    if (tid < 128) {
        const int b = tid >> 5;
        const int l = tid & 31;
        const int hwg = blockIdx.x * 32 + l;
        float s[LM];
        float mx = -1e30f;
#pragma unroll
        for (int m = 0; m < LM; m++) {
            float v = s_red[((0 * LM + m) * NB + b) * 32 + l]
                    + s_red[((1 * LM + m) * NB + b) * 32 + l]
                    + s_red[((2 * LM + m) * NB + b) * 32 + l]
                    + s_red[((3 * LM + m) * NB + b) * 32 + l];
            s[m] = v;
            mx = fmaxf(mx, v);
        }
        float sum = 0.0f;
#pragma unroll
        for (int m = 0; m < LM; m++) { s[m] = __expf(s[m] - mx); sum += s[m]; }
        const float inv = 1.0f / sum;
        float* ap = g_attn + (size_t)b * LM * HW + hwg;
#pragma unroll
        for (int m = 0; m < LM; m++) ap[(size_t)m * HW] = s[m] * inv;
    }
}

// ---------------------------------------------------------------------------
// Kernel 3: out[b][c][hw] = fm[b][c][hw] + 0.5*sum_m attn[b][m][hw]*val[m][c][hw]
// Block 256 = 32 hw lanes x 2 batch-groups x 4 hw-subtiles (128 hw per block).
// Each thread handles 2 batches (attn in 64 regs) -> val instruction
// replication only 2x (L1 absorbs it). Grid (32 hw-tiles, 12 c-chunks of 43).
// ---------------------------------------------------------------------------
__global__ __launch_bounds__(256) void out_kernel(
    const float* __restrict__ fm, const float* __restrict__ val,
    float* __restrict__ out) {
    const int tid  = threadIdx.x;
    const int lane = tid & 31;
    const int bg   = (tid >> 5) & 1;
    const int sub  = tid >> 6;
    const int hw   = blockIdx.x * 128 + sub * 32 + lane;
    const int c0   = blockIdx.y * 43;       // 516 = 12 * 43
    const int b0   = bg * 2;
    const int b1   = b0 + 1;

    float a0[LM], a1[LM];
    {
        const float* ap0 = g_attn + (size_t)b0 * LM * HW + hw;
        const float* ap1 = g_attn + (size_t)b1 * LM * HW + hw;
#pragma unroll
        for (int m = 0; m < LM; m++) {
            a0[m] = ap0[(size_t)m * HW];
            a1[m] = ap1[(size_t)m * HW];
        }
    }

    const float* fmp0 = fm + (size_t)b0 * DV * HW + hw;
    const float* fmp1 = fm + (size_t)b1 * DV * HW + hw;
    float*       op0  = out + (size_t)b0 * DV * HW + hw;
    float*       op1  = out + (size_t)b1 * DV * HW + hw;

#pragma unroll 2
    for (int cc = 0; cc < 43; cc++) {
        const int c = c0 + cc;
        const float* vp = val + (size_t)c * HW + hw;
        float s0 = 0.0f, s1 = 0.0f, t0 = 0.0f, t1 = 0.0f;
#pragma unroll
        for (int m = 0; m < LM; m += 2) {
            const float v0 = vp[(size_t)(m * DV) * HW];
            const float v1 = vp[(size_t)((m + 1) * DV) * HW];
            s0 += a0[m] * v0;     t0 += a1[m] * v0;
            s1 += a0[m + 1] * v1; t1 += a1[m + 1] * v1;
        }
        op0[(size_t)c * HW] = fmp0[(size_t)c * HW] + 0.5f * (s0 + s1);
        op1[(size_t)c * HW] = fmp1[(size_t)c * HW] + 0.5f * (t0 + t1);
    }
}

// ---------------------------------------------------------------------------
// Launch. Inputs (metadata order): fc, fm, key_buffer, value_buffer, Q, K, V.
// concat(new, buffer)[-32:] keeps exactly the buffers -> K and V matrices are
// dead inputs; only q = fc@Q survives.
// ---------------------------------------------------------------------------
extern "C" void kernel_launch(void* const* d_in, const int* in_sizes, int n_in,
                              void* d_out, int out_size) {
    const float* fc   = (const float*)d_in[0];
    const float* fm   = (const float*)d_in[1];
    const float* keyb = (const float*)d_in[2];
    const float* valb = (const float*)d_in[3];
    const float* Qm   = (const float*)d_in[4];
    float* out = (float*)d_out;

    const int red_bytes = DS * LM * NB * 32 * sizeof(float);   // 64KB
    cudaFuncSetAttribute(attn_kernel,
                         cudaFuncAttributeMaxDynamicSharedMemorySize, red_bytes);

    qproj_kernel<<<dim3(HW / 128, DK / 128, NB), 256>>>(fc, Qm);
    attn_kernel<<<dim3(HW / 32), 512, red_bytes>>>(keyb);
    out_kernel<<<dim3(HW / 128, 12), 256>>>(fm, valb, out);
}